// round 2
// baseline (speedup 1.0000x reference)
#include <cuda_runtime.h>
#include <cuda_bf16.h>
#include <math.h>

#define S_SPK   2
#define BATCH   16
#define T_LEN   300
#define C_CLS   3000
#define NSTATES 400
#define NARCS   1200
#define DSTATES 3000
#define DARCS   60000
#define NUMG    (S_SPK * BATCH)          // 32 numerator graphs
#define TOTARC  (DARCS + NUMG * NARCS)   // 98400

// ---------------- device scratch (no runtime allocation allowed) -------------
__device__ int   g_den_cnt[DSTATES];
__device__ int   g_den_rowptr[DSTATES + 1];
__device__ int   g_den_off[DSTATES];
__device__ int4  g_den_arcs[DARCS];                 // {src, label, w_bits, 0}

__device__ int   g_num_cnt[NUMG * NSTATES];
__device__ int   g_num_rowptr[NUMG * (NSTATES + 1)];
__device__ int   g_num_off[NUMG * NSTATES];
__device__ int4  g_num_arcs[NUMG * NARCS];

__device__ float g_den_llh[S_SPK * BATCH];          // [s][b]
__device__ float g_num_llh[S_SPK * S_SPK * BATCH];  // [s][g][b]

// ---------------- small helpers ---------------------------------------------
__device__ __forceinline__ float blk_reduce_max(float v, float* red) {
    __syncthreads();                       // protect red reuse
    const int lane = threadIdx.x & 31, wid = threadIdx.x >> 5;
#pragma unroll
    for (int o = 16; o; o >>= 1) v = fmaxf(v, __shfl_xor_sync(0xffffffffu, v, o));
    if (lane == 0) red[wid] = v;
    __syncthreads();
    if (wid == 0) {
        float x = red[lane];               // exactly 32 warps
#pragma unroll
        for (int o = 16; o; o >>= 1) x = fmaxf(x, __shfl_xor_sync(0xffffffffu, x, o));
        if (lane == 0) red[0] = x;
    }
    __syncthreads();
    return red[0];
}

__device__ __forceinline__ float blk_reduce_sum(float v, float* red) {
    __syncthreads();
    const int lane = threadIdx.x & 31, wid = threadIdx.x >> 5;
#pragma unroll
    for (int o = 16; o; o >>= 1) v += __shfl_xor_sync(0xffffffffu, v, o);
    if (lane == 0) red[wid] = v;
    __syncthreads();
    if (wid == 0) {
        float x = red[lane];
#pragma unroll
        for (int o = 16; o; o >>= 1) x += __shfl_xor_sync(0xffffffffu, x, o);
        if (lane == 0) red[0] = x;
    }
    __syncthreads();
    return red[0];
}

// Exclusive scan of cnt[0..n) into rowptr/off. 1024 threads, n <= 4096.
__device__ void block_scan(const int* cnt, int* rowptr, int* off, int n, int* wtot) {
    const int tid = threadIdx.x, lane = tid & 31, wid = tid >> 5;
    __syncthreads();
    const int base = tid * 4;
    int c0 = (base + 0 < n) ? cnt[base + 0] : 0;
    int c1 = (base + 1 < n) ? cnt[base + 1] : 0;
    int c2 = (base + 2 < n) ? cnt[base + 2] : 0;
    int c3 = (base + 3 < n) ? cnt[base + 3] : 0;
    int tsum = c0 + c1 + c2 + c3;
    int v = tsum;
#pragma unroll
    for (int o = 1; o < 32; o <<= 1) { int u = __shfl_up_sync(0xffffffffu, v, o); if (lane >= o) v += u; }
    if (lane == 31) wtot[wid] = v;
    __syncthreads();
    if (wid == 0) {
        int w = wtot[lane];
        int vv = w;
#pragma unroll
        for (int o = 1; o < 32; o <<= 1) { int u = __shfl_up_sync(0xffffffffu, vv, o); if (lane >= o) vv += u; }
        wtot[lane] = vv - w;
        if (lane == 31) wtot[32] = vv;
    }
    __syncthreads();
    int ex = wtot[wid] + (v - tsum);
    if (base + 0 < n) { rowptr[base + 0] = ex; off[base + 0] = ex; } ex += c0;
    if (base + 1 < n) { rowptr[base + 1] = ex; off[base + 1] = ex; } ex += c1;
    if (base + 2 < n) { rowptr[base + 2] = ex; off[base + 2] = ex; } ex += c2;
    if (base + 3 < n) { rowptr[base + 3] = ex; off[base + 3] = ex; } ex += c3;
    if (tid == 0) rowptr[n] = wtot[32];
}

// ---------------- CSR build kernels ------------------------------------------
__global__ void zero_kernel() {
    int i = blockIdx.x * 1024 + threadIdx.x;
    if (i < DSTATES) g_den_cnt[i] = 0;
    if (i < NUMG * NSTATES) g_num_cnt[i] = 0;
}

__global__ void hist_kernel(const int* __restrict__ den_dst, const int* __restrict__ num_dst) {
    int i = blockIdx.x * 1024 + threadIdx.x;
    if (i < DARCS) {
        atomicAdd(&g_den_cnt[den_dst[i]], 1);
    } else {
        int j = i - DARCS;
        if (j < NUMG * NARCS) {
            int g = j / NARCS;
            atomicAdd(&g_num_cnt[g * NSTATES + num_dst[j]], 1);
        }
    }
}

__global__ void scan_kernel() {
    __shared__ int wtot[33];
    block_scan(g_den_cnt, g_den_rowptr, g_den_off, DSTATES, wtot);
    for (int g = 0; g < NUMG; g++)
        block_scan(g_num_cnt + g * NSTATES, g_num_rowptr + g * (NSTATES + 1),
                   g_num_off + g * NSTATES, NSTATES, wtot);
}

__global__ void scatter_kernel(const int* __restrict__ den_src, const int* __restrict__ den_dst,
                               const int* __restrict__ den_lab, const float* __restrict__ den_w,
                               const int* __restrict__ num_src, const int* __restrict__ num_dst,
                               const int* __restrict__ num_lab, const float* __restrict__ num_w) {
    int i = blockIdx.x * 1024 + threadIdx.x;
    if (i < DARCS) {
        int d = den_dst[i];
        int pos = atomicAdd(&g_den_off[d], 1);
        g_den_arcs[pos] = make_int4(den_src[i], den_lab[i], __float_as_int(den_w[i]), 0);
    } else {
        int j = i - DARCS;
        if (j < NUMG * NARCS) {
            int g = j / NARCS;
            int d = num_dst[j];
            int pos = atomicAdd(&g_num_off[g * NSTATES + d], 1);
            g_num_arcs[g * NARCS + pos] = make_int4(num_src[j], num_lab[j], __float_as_int(num_w[j]), 0);
        }
    }
}

// ---------------- fused forward kernel ---------------------------------------
// blocks 0..31  : denominator, one (s,b) each
// blocks 32..95 : numerator,  one (s,g,b) each
__global__ __launch_bounds__(1024, 1)
void forward_kernel(const float* __restrict__ est, const int* __restrict__ seqlen,
                    const float* __restrict__ num_start, const float* __restrict__ num_final,
                    const float* __restrict__ den_start, const float* __restrict__ den_final) {
    __shared__ float sBufA[DSTATES];
    __shared__ float sBufB[DSTATES];
    __shared__ float sLLH[C_CLS];
    __shared__ float sRed[32];

    const int tid = threadIdx.x;
    const int bid = blockIdx.x;

    if (bid < S_SPK * BATCH) {
        // ------------------- DENOMINATOR -------------------
        const int s = bid >> 4, b = bid & 15;
        const int L = seqlen[b];
        const float* llh = est + (size_t)(s * BATCH + b) * T_LEN * C_CLS;

        float* a  = sBufA;
        float* an = sBufB;
        for (int i = tid; i < DSTATES; i += 1024) a[i] = den_start[i];

        // hoist per-thread CSR ranges (strided states tid, tid+1024, tid+2048)
        const int st0 = tid, st1 = tid + 1024, st2 = tid + 2048;
        const int b0 = __ldg(&g_den_rowptr[st0]), e0 = __ldg(&g_den_rowptr[st0 + 1]);
        const int b1 = __ldg(&g_den_rowptr[st1]), e1 = __ldg(&g_den_rowptr[st1 + 1]);
        const bool has2 = (st2 < DSTATES);
        const int b2 = has2 ? __ldg(&g_den_rowptr[st2]) : 0;
        const int e2 = has2 ? __ldg(&g_den_rowptr[st2 + 1]) : 0;

        __syncthreads();
        double C = 0.0;

        for (int t = 0; t < L; t++) {
            float m = -3.4e38f;
            for (int i = tid; i < DSTATES; i += 1024) m = fmaxf(m, a[i]);
            const float M = blk_reduce_max(m, sRed);

            const float* row = llh + (size_t)t * C_CLS;
            for (int i = tid; i < C_CLS; i += 1024) sLLH[i] = row[i];
            __syncthreads();

            float acc0 = 0.f, acc1 = 0.f, acc2 = 0.f;
            for (int k = b0; k < e0; k++) {
                int4 arc = __ldg(&g_den_arcs[k]);
                acc0 += __expf(a[arc.x] - M + __int_as_float(arc.z) + sLLH[arc.y]);
            }
            for (int k = b1; k < e1; k++) {
                int4 arc = __ldg(&g_den_arcs[k]);
                acc1 += __expf(a[arc.x] - M + __int_as_float(arc.z) + sLLH[arc.y]);
            }
            for (int k = b2; k < e2; k++) {
                int4 arc = __ldg(&g_den_arcs[k]);
                acc2 += __expf(a[arc.x] - M + __int_as_float(arc.z) + sLLH[arc.y]);
            }
            an[st0] = (acc0 > 0.f) ? __logf(acc0) : -1e30f;
            an[st1] = (acc1 > 0.f) ? __logf(acc1) : -1e30f;
            if (has2) an[st2] = (acc2 > 0.f) ? __logf(acc2) : -1e30f;
            __syncthreads();

            C += (double)M;
            float* tmp = a; a = an; an = tmp;
        }

        float m2 = -3.4e38f;
        for (int i = tid; i < DSTATES; i += 1024) m2 = fmaxf(m2, a[i] + den_final[i]);
        const float M2 = blk_reduce_max(m2, sRed);
        float ssum = 0.f;
        for (int i = tid; i < DSTATES; i += 1024) ssum += __expf(a[i] + den_final[i] - M2);
        const float S2 = blk_reduce_sum(ssum, sRed);
        if (tid == 0) g_den_llh[bid] = (float)(C + (double)M2 + log((double)S2));
    } else {
        // ------------------- NUMERATOR -------------------
        int r = bid - S_SPK * BATCH;            // r in [0,64)
        const int s = r >> 5; r &= 31;
        const int g = r >> 4;
        const int b = r & 15;
        const int L = seqlen[b];
        const int gb = g * BATCH + b;

        const float* llh = est + (size_t)(s * BATCH + b) * T_LEN * C_CLS;
        const float* st_w = num_start + (size_t)gb * NSTATES;
        const float* fn_w = num_final + (size_t)gb * NSTATES;
        const int*   rp   = g_num_rowptr + gb * (NSTATES + 1);
        const int4*  arcs = g_num_arcs + (size_t)gb * NARCS;

        float* a  = sBufA;
        float* an = sBufB;
        if (tid < NSTATES) a[tid] = st_w[tid];

        const int ab = (tid < NSTATES) ? __ldg(&rp[tid]) : 0;
        const int ae = (tid < NSTATES) ? __ldg(&rp[tid + 1]) : 0;

        __syncthreads();
        double C = 0.0;

        for (int t = 0; t < L; t++) {
            float m = (tid < NSTATES) ? a[tid] : -3.4e38f;
            const float M = blk_reduce_max(m, sRed);
            const float* row = llh + (size_t)t * C_CLS;

            if (tid < NSTATES) {
                float acc = 0.f;
                for (int k = ab; k < ae; k++) {
                    int4 arc = __ldg(&arcs[k]);
                    acc += __expf(a[arc.x] - M + __int_as_float(arc.z) + __ldg(&row[arc.y]));
                }
                an[tid] = (acc > 0.f) ? __logf(acc) : -1e30f;
            }
            __syncthreads();
            C += (double)M;
            float* tmp = a; a = an; an = tmp;
        }

        float m2 = (tid < NSTATES) ? (a[tid] + fn_w[tid]) : -3.4e38f;
        const float M2 = blk_reduce_max(m2, sRed);
        float ssum = (tid < NSTATES) ? __expf(a[tid] + fn_w[tid] - M2) : 0.f;
        const float S2 = blk_reduce_sum(ssum, sRed);
        if (tid == 0) g_num_llh[(s * S_SPK + g) * BATCH + b] = (float)(C + (double)M2 + log((double)S2));
    }
}

// ---------------- combine: permutation argmax + loss --------------------------
__global__ void combine_kernel(float* out) {
    if (threadIdx.x == 0 && blockIdx.x == 0) {
        double loss = 0.0;
        for (int b = 0; b < BATCH; b++) {
            float n00 = g_num_llh[(0 * S_SPK + 0) * BATCH + b];  // s=0, g=0
            float n01 = g_num_llh[(0 * S_SPK + 1) * BATCH + b];  // s=0, g=1
            float n10 = g_num_llh[(1 * S_SPK + 0) * BATCH + b];  // s=1, g=0
            float n11 = g_num_llh[(1 * S_SPK + 1) * BATCH + b];  // s=1, g=1
            float p0 = n00 + n11;     // perm (0,1)
            float p1 = n01 + n10;     // perm (1,0)
            float a0, a1;
            if (p1 > p0) { a0 = n01; a1 = n10; } else { a0 = n00; a1 = n11; }
            loss -= (double)a0 - (double)g_den_llh[0 * BATCH + b];
            loss -= (double)a1 - (double)g_den_llh[1 * BATCH + b];
        }
        out[0] = (float)loss;
    }
}

// ---------------- launch ------------------------------------------------------
extern "C" void kernel_launch(void* const* d_in, const int* in_sizes, int n_in,
                              void* d_out, int out_size) {
    const float* est        = (const float*)d_in[0];
    const int*   seqlen     = (const int*)  d_in[1];
    const int*   num_src    = (const int*)  d_in[2];
    const int*   num_dst    = (const int*)  d_in[3];
    const int*   num_label  = (const int*)  d_in[4];
    const float* num_weight = (const float*)d_in[5];
    const float* num_start  = (const float*)d_in[6];
    const float* num_final  = (const float*)d_in[7];
    const int*   den_src    = (const int*)  d_in[8];
    const int*   den_dst    = (const int*)  d_in[9];
    const int*   den_label  = (const int*)  d_in[10];
    const float* den_weight = (const float*)d_in[11];
    const float* den_start  = (const float*)d_in[12];
    const float* den_final  = (const float*)d_in[13];

    zero_kernel<<<(NUMG * NSTATES + 1023) / 1024, 1024>>>();
    hist_kernel<<<(TOTARC + 1023) / 1024, 1024>>>(den_dst, num_dst);
    scan_kernel<<<1, 1024>>>();
    scatter_kernel<<<(TOTARC + 1023) / 1024, 1024>>>(den_src, den_dst, den_label, den_weight,
                                                     num_src, num_dst, num_label, num_weight);
    forward_kernel<<<S_SPK * BATCH + S_SPK * S_SPK * BATCH, 1024>>>(
        est, seqlen, num_start, num_final, den_start, den_final);
    combine_kernel<<<1, 32>>>((float*)d_out);
}

// round 6
// speedup vs baseline: 2.4029x; 2.4029x over previous
#include <cuda_runtime.h>
#include <cuda_bf16.h>
#include <math.h>

#define S_SPK   2
#define BATCH   16
#define T_LEN   300
#define C_CLS   3000
#define NSTATES 400
#define NARCS   1200
#define DSTATES 3000
#define DARCS   60000
#define DHALF   1500                      // den states per cluster CTA
#define NUMG    (S_SPK * BATCH)           // 32 numerator graphs
#define TOTARC  (DARCS + NUMG * NARCS)    // 98400

// ---------------- device scratch (no runtime allocation allowed) -------------
__device__ int   g_den_cnt[DSTATES];
__device__ int   g_den_rowptr[DSTATES + 1];
__device__ int   g_den_off[DSTATES];
__device__ uint2 g_den_arcs[DARCS];                 // {src | lab<<16, exp(w) bits}

__device__ int   g_num_cnt[NUMG * NSTATES];
__device__ int   g_num_rowptr[NUMG * (NSTATES + 1)];
__device__ int   g_num_off[NUMG * NSTATES];
__device__ int4  g_num_arcs[NUMG * NARCS];          // {src, label, w_bits, 0}

__device__ float g_den_llh[S_SPK * BATCH];          // [s][b]
__device__ float g_num_llh[S_SPK * S_SPK * BATCH];  // [s][g][b]

// ---------------- cluster helpers --------------------------------------------
__device__ __forceinline__ unsigned smem_u32(const void* p) {
    unsigned a;
    asm("{ .reg .u64 t; cvta.to.shared.u64 t, %1; cvt.u32.u64 %0, t; }" : "=r"(a) : "l"(p));
    return a;
}
__device__ __forceinline__ unsigned mapa_sh(unsigned local, unsigned rank) {
    unsigned r;
    asm("mapa.shared::cluster.u32 %0, %1, %2;" : "=r"(r) : "r"(local), "r"(rank));
    return r;
}
__device__ __forceinline__ void st_cluster_f32(unsigned addr, float v) {
    asm volatile("st.shared::cluster.f32 [%0], %1;" :: "r"(addr), "f"(v));
}
__device__ __forceinline__ void cluster_sync() {
    asm volatile("barrier.cluster.arrive.aligned;" ::: "memory");
    asm volatile("barrier.cluster.wait.aligned;"   ::: "memory");
}

// ---------------- block reductions -------------------------------------------
__device__ __forceinline__ float blk_reduce_max(float v, float* red) {
    __syncthreads();
    const int lane = threadIdx.x & 31, wid = threadIdx.x >> 5;
#pragma unroll
    for (int o = 16; o; o >>= 1) v = fmaxf(v, __shfl_xor_sync(0xffffffffu, v, o));
    if (lane == 0) red[wid] = v;
    __syncthreads();
    if (wid == 0) {
        float x = red[lane];
#pragma unroll
        for (int o = 16; o; o >>= 1) x = fmaxf(x, __shfl_xor_sync(0xffffffffu, x, o));
        if (lane == 0) red[0] = x;
    }
    __syncthreads();
    return red[0];
}

__device__ __forceinline__ float blk_reduce_sum(float v, float* red) {
    __syncthreads();
    const int lane = threadIdx.x & 31, wid = threadIdx.x >> 5;
#pragma unroll
    for (int o = 16; o; o >>= 1) v += __shfl_xor_sync(0xffffffffu, v, o);
    if (lane == 0) red[wid] = v;
    __syncthreads();
    if (wid == 0) {
        float x = red[lane];
#pragma unroll
        for (int o = 16; o; o >>= 1) x += __shfl_xor_sync(0xffffffffu, x, o);
        if (lane == 0) red[0] = x;
    }
    __syncthreads();
    return red[0];
}

// Exclusive scan of cnt[0..n) into rowptr/off. 1024 threads, n <= 4096.
__device__ void block_scan(const int* cnt, int* rowptr, int* off, int n, int* wtot) {
    const int tid = threadIdx.x, lane = tid & 31, wid = tid >> 5;
    __syncthreads();
    const int base = tid * 4;
    int c0 = (base + 0 < n) ? cnt[base + 0] : 0;
    int c1 = (base + 1 < n) ? cnt[base + 1] : 0;
    int c2 = (base + 2 < n) ? cnt[base + 2] : 0;
    int c3 = (base + 3 < n) ? cnt[base + 3] : 0;
    int tsum = c0 + c1 + c2 + c3;
    int v = tsum;
#pragma unroll
    for (int o = 1; o < 32; o <<= 1) { int u = __shfl_up_sync(0xffffffffu, v, o); if (lane >= o) v += u; }
    if (lane == 31) wtot[wid] = v;
    __syncthreads();
    if (wid == 0) {
        int w = wtot[lane];
        int vv = w;
#pragma unroll
        for (int o = 1; o < 32; o <<= 1) { int u = __shfl_up_sync(0xffffffffu, vv, o); if (lane >= o) vv += u; }
        wtot[lane] = vv - w;
        if (lane == 31) wtot[32] = vv;
    }
    __syncthreads();
    int ex = wtot[wid] + (v - tsum);
    if (base + 0 < n) { rowptr[base + 0] = ex; off[base + 0] = ex; } ex += c0;
    if (base + 1 < n) { rowptr[base + 1] = ex; off[base + 1] = ex; } ex += c1;
    if (base + 2 < n) { rowptr[base + 2] = ex; off[base + 2] = ex; } ex += c2;
    if (base + 3 < n) { rowptr[base + 3] = ex; off[base + 3] = ex; } ex += c3;
    if (tid == 0) rowptr[n] = wtot[32];
}

// ---------------- CSR build --------------------------------------------------
__global__ void zero_kernel() {
    int i = blockIdx.x * 1024 + threadIdx.x;
    if (i < DSTATES) g_den_cnt[i] = 0;
    if (i < NUMG * NSTATES) g_num_cnt[i] = 0;
}

__global__ void hist_kernel(const int* __restrict__ den_dst, const int* __restrict__ num_dst) {
    int i = blockIdx.x * 1024 + threadIdx.x;
    if (i < DARCS) {
        atomicAdd(&g_den_cnt[den_dst[i]], 1);
    } else {
        int j = i - DARCS;
        if (j < NUMG * NARCS) {
            int g = j / NARCS;
            atomicAdd(&g_num_cnt[g * NSTATES + num_dst[j]], 1);
        }
    }
}

__global__ void scan_kernel() {
    __shared__ int wtot[33];
    if (blockIdx.x == 0) {
        block_scan(g_den_cnt, g_den_rowptr, g_den_off, DSTATES, wtot);
    } else {
        int g = blockIdx.x - 1;
        block_scan(g_num_cnt + g * NSTATES, g_num_rowptr + g * (NSTATES + 1),
                   g_num_off + g * NSTATES, NSTATES, wtot);
    }
}

__global__ void scatter_kernel(const int* __restrict__ den_src, const int* __restrict__ den_dst,
                               const int* __restrict__ den_lab, const float* __restrict__ den_w,
                               const int* __restrict__ num_src, const int* __restrict__ num_dst,
                               const int* __restrict__ num_lab, const float* __restrict__ num_w) {
    int i = blockIdx.x * 1024 + threadIdx.x;
    if (i < DARCS) {
        int d = den_dst[i];
        int pos = atomicAdd(&g_den_off[d], 1);
        unsigned packed = (unsigned)den_src[i] | ((unsigned)den_lab[i] << 16);
        g_den_arcs[pos] = make_uint2(packed, __float_as_uint(__expf(den_w[i])));
    } else {
        int j = i - DARCS;
        if (j < NUMG * NARCS) {
            int g = j / NARCS;
            int d = num_dst[j];
            int pos = atomicAdd(&g_num_off[g * NSTATES + d], 1);
            g_num_arcs[g * NARCS + pos] = make_int4(num_src[j], num_lab[j], __float_as_int(num_w[j]), 0);
        }
    }
}

// ---------------- fused forward kernel ----------------------------------------
// blocks 0..63  : denominator, 2 CTAs (one cluster) per (s,b); CTA owns 1500 dst states
// blocks 64..127: numerator, one (s,g,b) each (log-domain, small)
__global__ void __cluster_dims__(2, 1, 1) __launch_bounds__(1024, 1)
forward_kernel(const float* __restrict__ est, const int* __restrict__ seqlen,
               const float* __restrict__ num_start, const float* __restrict__ num_final,
               const float* __restrict__ den_start, const float* __restrict__ den_final) {
    __shared__ float sA[DSTATES];
    __shared__ float sB[DSTATES];
    __shared__ float sP[C_CLS];
    __shared__ float sRed[32];
    __shared__ float sMax[2][2];          // [parity][rank]

    const int tid = threadIdx.x;
    const int bid = blockIdx.x;

    if (bid < 2 * S_SPK * BATCH) {
        // ------------------- DENOMINATOR (linear domain, cluster of 2) -------
        const int rank = bid & 1;
        const int seq  = bid >> 1;               // 0..31
        const int s = seq >> 4, b = seq & 15;
        const int L = seqlen[b];
        const float* llh = est + (size_t)(s * BATCH + b) * T_LEN * C_CLS;

        // remote smem bases on peer CTA
        const unsigned peer = rank ^ 1;
        const unsigned rA = mapa_sh(smem_u32(sA), peer);
        const unsigned rB = mapa_sh(smem_u32(sB), peer);
        const unsigned rM = mapa_sh(smem_u32(&sMax[0][0]), peer);

        // init: q0 = exp(start), both CTAs hold the full array
        float m0 = 0.f;
        for (int i = tid; i < DSTATES; i += 1024) {
            float v = __expf(den_start[i]);
            sA[i] = v;
            m0 = fmaxf(m0, v);
        }
        float g = blk_reduce_max(m0, sRed);

        // this CTA's dst states: st0 = base+tid (always), st1 = base+1024+tid (tid<476)
        const int base = rank * DHALF;
        const int st0 = base + tid;
        const bool has1 = (tid < DHALF - 1024);
        const int st1 = st0 + 1024;
        const int b0 = __ldg(&g_den_rowptr[st0]), e0 = __ldg(&g_den_rowptr[st0 + 1]);
        const int b1 = has1 ? __ldg(&g_den_rowptr[st1]) : 0;
        const int e1 = has1 ? __ldg(&g_den_rowptr[st1 + 1]) : 0;

        cluster_sync();                            // peer smem ready

        float* qp = sA;  float* qn = sB;
        unsigned rqn = rB;                         // peer address of qn
        double C = 0.0;

        for (int t = 0; t < L; t++) {
            const float inv = 1.0f / g;
            C += (double)__logf(g);

            // stage P = exp(llh_row) : 750 float4 loads
            if (tid < C_CLS / 4) {
                float4 v = __ldg((const float4*)(llh + (size_t)t * C_CLS) + tid);
                ((float4*)sP)[tid] = make_float4(__expf(v.x), __expf(v.y),
                                                 __expf(v.z), __expf(v.w));
            }
            __syncthreads();

            // gather: acc = sum_{arcs into st} q[src] * exp(w) * P[lab]
            float acc0 = 0.f, acc1 = 0.f;
#pragma unroll 4
            for (int k = b0; k < e0; k++) {
                uint2 arc = __ldg(&g_den_arcs[k]);
                acc0 += qp[arc.x & 0xFFFFu] * __uint_as_float(arc.y) * sP[arc.x >> 16];
            }
#pragma unroll 4
            for (int k = b1; k < e1; k++) {
                uint2 arc = __ldg(&g_den_arcs[k]);
                acc1 += qp[arc.x & 0xFFFFu] * __uint_as_float(arc.y) * sP[arc.x >> 16];
            }
            acc0 *= inv;
            acc1 *= inv;

            float m = has1 ? fmaxf(acc0, acc1) : acc0;
            const float M = blk_reduce_max(m, sRed);

            // publish own half to both CTAs
            qn[st0] = acc0;
            st_cluster_f32(rqn + (unsigned)st0 * 4u, acc0);
            if (has1) {
                qn[st1] = acc1;
                st_cluster_f32(rqn + (unsigned)st1 * 4u, acc1);
            }
            const int p = t & 1;
            if (tid == 0) {
                sMax[p][rank] = M;
                st_cluster_f32(rM + (unsigned)(p * 2 + rank) * 4u, M);
            }
            cluster_sync();

            g = fmaxf(sMax[p][0], sMax[p][1]);
            float* tp = qp; qp = qn; qn = tp;
            rqn = (qn == sA) ? rA : rB;
        }

        // logZ = C + log( sum_i q[i]*exp(final_i) )
        float ssum = 0.f;
        for (int i = tid; i < DSTATES; i += 1024)
            ssum += qp[i] * __expf(den_final[i]);
        const float S2 = blk_reduce_sum(ssum, sRed);
        if (tid == 0 && rank == 0)
            g_den_llh[seq] = (float)(C + log((double)S2));
        cluster_sync();                            // keep peer smem alive until both done
    } else {
        // ------------------- NUMERATOR (log domain, as before) ---------------
        int r = bid - 2 * S_SPK * BATCH;           // r in [0,64)
        const int s = r >> 5; r &= 31;
        const int g = r >> 4;
        const int b = r & 15;
        const int L = seqlen[b];
        const int gb = g * BATCH + b;

        const float* llh = est + (size_t)(s * BATCH + b) * T_LEN * C_CLS;
        const float* st_w = num_start + (size_t)gb * NSTATES;
        const float* fn_w = num_final + (size_t)gb * NSTATES;
        const int*   rp   = g_num_rowptr + gb * (NSTATES + 1);
        const int4*  arcs = g_num_arcs + (size_t)gb * NARCS;

        float* a  = sA;
        float* an = sB;
        if (tid < NSTATES) a[tid] = st_w[tid];

        const int ab = (tid < NSTATES) ? __ldg(&rp[tid]) : 0;
        const int ae = (tid < NSTATES) ? __ldg(&rp[tid + 1]) : 0;

        __syncthreads();
        double C = 0.0;

        for (int t = 0; t < L; t++) {
            float m = (tid < NSTATES) ? a[tid] : -3.4e38f;
            const float M = blk_reduce_max(m, sRed);
            const float* row = llh + (size_t)t * C_CLS;

            if (tid < NSTATES) {
                float acc = 0.f;
#pragma unroll 2
                for (int k = ab; k < ae; k++) {
                    int4 arc = __ldg(&arcs[k]);
                    acc += __expf(a[arc.x] - M + __int_as_float(arc.z) + __ldg(&row[arc.y]));
                }
                an[tid] = (acc > 0.f) ? __logf(acc) : -1e30f;
            }
            __syncthreads();
            C += (double)M;
            float* tmp = a; a = an; an = tmp;
        }

        float m2 = (tid < NSTATES) ? (a[tid] + fn_w[tid]) : -3.4e38f;
        const float M2 = blk_reduce_max(m2, sRed);
        float ssum = (tid < NSTATES) ? __expf(a[tid] + fn_w[tid] - M2) : 0.f;
        const float S2 = blk_reduce_sum(ssum, sRed);
        if (tid == 0)
            g_num_llh[(s * S_SPK + g) * BATCH + b] = (float)(C + (double)M2 + log((double)S2));
    }
}

// ---------------- combine: permutation argmax + loss --------------------------
__global__ void combine_kernel(float* out) {
    if (threadIdx.x == 0 && blockIdx.x == 0) {
        double loss = 0.0;
        for (int b = 0; b < BATCH; b++) {
            float n00 = g_num_llh[(0 * S_SPK + 0) * BATCH + b];
            float n01 = g_num_llh[(0 * S_SPK + 1) * BATCH + b];
            float n10 = g_num_llh[(1 * S_SPK + 0) * BATCH + b];
            float n11 = g_num_llh[(1 * S_SPK + 1) * BATCH + b];
            float p0 = n00 + n11;
            float p1 = n01 + n10;
            float a0, a1;
            if (p1 > p0) { a0 = n01; a1 = n10; } else { a0 = n00; a1 = n11; }
            loss -= (double)a0 - (double)g_den_llh[0 * BATCH + b];
            loss -= (double)a1 - (double)g_den_llh[1 * BATCH + b];
        }
        out[0] = (float)loss;
    }
}

// ---------------- launch ------------------------------------------------------
extern "C" void kernel_launch(void* const* d_in, const int* in_sizes, int n_in,
                              void* d_out, int out_size) {
    const float* est        = (const float*)d_in[0];
    const int*   seqlen     = (const int*)  d_in[1];
    const int*   num_src    = (const int*)  d_in[2];
    const int*   num_dst    = (const int*)  d_in[3];
    const int*   num_label  = (const int*)  d_in[4];
    const float* num_weight = (const float*)d_in[5];
    const float* num_start  = (const float*)d_in[6];
    const float* num_final  = (const float*)d_in[7];
    const int*   den_src    = (const int*)  d_in[8];
    const int*   den_dst    = (const int*)  d_in[9];
    const int*   den_label  = (const int*)  d_in[10];
    const float* den_weight = (const float*)d_in[11];
    const float* den_start  = (const float*)d_in[12];
    const float* den_final  = (const float*)d_in[13];

    zero_kernel<<<(NUMG * NSTATES + 1023) / 1024, 1024>>>();
    hist_kernel<<<(TOTARC + 1023) / 1024, 1024>>>(den_dst, num_dst);
    scan_kernel<<<1 + NUMG, 1024>>>();
    scatter_kernel<<<(TOTARC + 1023) / 1024, 1024>>>(den_src, den_dst, den_label, den_weight,
                                                     num_src, num_dst, num_label, num_weight);
    forward_kernel<<<2 * S_SPK * BATCH + S_SPK * S_SPK * BATCH, 1024>>>(
        est, seqlen, num_start, num_final, den_start, den_final);
    combine_kernel<<<1, 32>>>((float*)d_out);
}